// round 15
// baseline (speedup 1.0000x reference)
#include <cuda_runtime.h>
#include <cuda_fp16.h>
#include <cstdint>

// CARAFE: conv3x3 via single-pass fp16 mma.sync implicit GEMM (M=128 tiles,
// K-split x3, pre-shifted x copies), combine+bias+relu fused into
// conv1x1+softmax (vectorized, fp16 kern out), then 5x5 reassembly +
// pixel_shuffle(2).
// x(4,256,64,64) w1(64,256,3,3) b1(64) w2(100,64) b2(100) -> out(4,256,128,128)

#define B_   4
#define C_   256
#define H_   64
#define W_   64
#define CMID 64
#define NK   100
#define NSPLIT 4
#define CSPL (C_ / NSPLIT)

#define KTOT   (C_ * 9)     // 2304
#define KC     64           // k per staged chunk
#define NCHUNK (KTOT / KC)  // 36
#define KSPLIT 3
#define CHPS   (NCHUNK / KSPLIT)  // 12 chunks per CTA

#define NX (B_ * C_ * H_ * W_)   // 4194304
#define NW (CMID * KTOT)         // 147456

// scratch
__device__ float  g_feat_part[KSPLIT * B_ * CMID * H_ * W_];  // 12 MB
__device__ __half g_kh[B_ * NK * H_ * W_];                    // fp16 kern
__device__ __half g_xs[3 * NX];     // 24 MB: kw-shifted fp16 x copies
__device__ __half g_wh[NW];

__device__ __forceinline__ uint32_t s2u(const void* p) {
    uint32_t a;
    asm("{ .reg .u64 t; cvta.to.shared.u64 t, %1; cvt.u32.u64 %0, t; }"
        : "=r"(a) : "l"(p));
    return a;
}
__device__ __forceinline__ void ldsm4(uint32_t* r, uint32_t addr) {
    asm volatile("ldmatrix.sync.aligned.m8n8.x4.shared.b16 {%0,%1,%2,%3}, [%4];"
                 : "=r"(r[0]), "=r"(r[1]), "=r"(r[2]), "=r"(r[3]) : "r"(addr));
}
__device__ __forceinline__ void ldsm4t(uint32_t* r, uint32_t addr) {
    asm volatile("ldmatrix.sync.aligned.m8n8.x4.trans.shared.b16 {%0,%1,%2,%3}, [%4];"
                 : "=r"(r[0]), "=r"(r[1]), "=r"(r[2]), "=r"(r[3]) : "r"(addr));
}
__device__ __forceinline__ void mma16816(float* d, const uint32_t* a,
                                         uint32_t b0, uint32_t b1) {
    asm volatile(
        "mma.sync.aligned.m16n8k16.row.col.f32.f16.f16.f32 "
        "{%0,%1,%2,%3}, {%4,%5,%6,%7}, {%8,%9}, {%0,%1,%2,%3};"
        : "+f"(d[0]), "+f"(d[1]), "+f"(d[2]), "+f"(d[3])
        : "r"(a[0]), "r"(a[1]), "r"(a[2]), "r"(a[3]), "r"(b0), "r"(b1));
}
__device__ __forceinline__ uint32_t pack2(__half a, __half b) {
    return (uint32_t)__half_as_ushort(a) | ((uint32_t)__half_as_ushort(b) << 16);
}

// ---------------------------------------------------------------------------
// Kernel 0: build g_wh and the 3 kw-shifted fp16 copies of x.
// ---------------------------------------------------------------------------
__global__ void convert_kernel(const float* __restrict__ x,
                               const float* __restrict__ w1)
{
    const int stride = gridDim.x * blockDim.x;
    const int tid0 = blockIdx.x * blockDim.x + threadIdx.x;

    for (int i = tid0; i < NW; i += stride)
        g_wh[i] = __float2half_rn(w1[i]);

    const int HALF_NX = NX / 2;
    const int n2 = 3 * HALF_NX;
    for (int i = tid0; i < n2; i += stride) {
        int kw  = i / HALF_NX;
        int rem = i - kw * HALF_NX;
        int wp  = rem & 31;
        int row = rem >> 5;
        int w0  = 2 * wp + kw - 1;
        const float* src = x + (size_t)row * W_;
        float v0 = ((unsigned)w0 < W_)       ? src[w0]     : 0.f;
        float v1 = ((unsigned)(w0 + 1) < W_) ? src[w0 + 1] : 0.f;
        uint32_t packed = pack2(__float2half_rn(v0), __float2half_rn(v1));
        *reinterpret_cast<uint32_t*>(g_xs + (size_t)kw * NX + (size_t)row * W_
                                     + 2 * wp) = packed;
    }
}

// ---------------------------------------------------------------------------
// Kernel 1: conv3x3 partial (12 K-chunks) as fp16 HMMA implicit GEMM.
// ---------------------------------------------------------------------------
__global__ __launch_bounds__(256, 2) void conv3x3_hmma_kernel()
{
    __shared__ __half ATh[KC][136];     // [k][128 px + pad]
    __shared__ __half Bsh[CMID][72];    // [n][k]

    const int tid  = threadIdx.x;
    const int lane = tid & 31;
    const int wid  = tid >> 5;

    const int bx   = blockIdx.x;
    const int b    = bx / (32 * KSPLIT);
    const int rem  = bx % (32 * KSPLIT);
    const int hp   = rem / KSPLIT;
    const int ksp  = rem % KSPLIT;
    const int h0   = hp * 2;

    const int m0 = (wid & 3) * 16;
    const int n0 = (wid >> 2) * 32;

    const int lrow  = (lane & 7) + ((lane >> 4) & 1) * 8;
    const int lcol8 = ((lane >> 3) & 1) * 8;

    const uint32_t sATh = s2u(ATh);
    const uint32_t sBh  = s2u(Bsh);

    float acc[2][4][4];
#pragma unroll
    for (int i = 0; i < 2; i++)
#pragma unroll
        for (int j = 0; j < 4; j++)
#pragma unroll
            for (int t = 0; t < 4; t++) acc[i][j][t] = 0.f;

    for (int chk = ksp * CHPS; chk < (ksp + 1) * CHPS; chk++) {
        const int k0 = chk * KC;

#pragma unroll
        for (int t = 0; t < 4; t++) {
            int idx = tid + (t << 8);
            int kk  = idx >> 4;
            int seg = idx & 15;
            int k   = k0 + kk;
            int c   = k / 9;
            int r   = k - c * 9;
            int kh  = r / 3;
            int kw  = r - kh * 3;
            int y   = h0 + (seg >> 3) + kh - 1;
            uint4 v = make_uint4(0u, 0u, 0u, 0u);
            if ((unsigned)y < H_)
                v = *reinterpret_cast<const uint4*>(
                    g_xs + ((size_t)kw * NX)
                         + (((size_t)(b * C_ + c) * H_ + y) * W_)
                         + (seg & 7) * 8);
            *reinterpret_cast<uint4*>(&ATh[kk][seg * 8]) = v;
        }
        {
            int n  = tid >> 2;
            int kq = tid & 3;
            const uint4* ph = reinterpret_cast<const uint4*>(
                g_wh + (size_t)n * KTOT + k0 + kq * 16);
            uint4 w0 = ph[0], w1v = ph[1];
            *reinterpret_cast<uint4*>(&Bsh[n][kq * 16])     = w0;
            *reinterpret_cast<uint4*>(&Bsh[n][kq * 16 + 8]) = w1v;
        }
        __syncthreads();

#pragma unroll
        for (int ks = 0; ks < 4; ks++) {
            uint32_t arow = (uint32_t)((ks * 16 + lrow) * 136);
            uint32_t ah0[4], ah1[4];
            ldsm4t(ah0, sATh + (arow + m0 + lcol8) * 2);
            ldsm4t(ah1, sATh + (arow + m0 + 64 + lcol8) * 2);
#pragma unroll
            for (int hn = 0; hn < 2; hn++) {
                uint32_t boff = (uint32_t)(((n0 + hn * 16 + lrow) * 72
                                            + ks * 16 + lcol8) * 2);
                uint32_t bh[4];
                ldsm4(bh, sBh + boff);
                int nt = hn * 2;
                mma16816(acc[0][nt],     ah0, bh[0], bh[1]);
                mma16816(acc[0][nt + 1], ah0, bh[2], bh[3]);
                mma16816(acc[1][nt],     ah1, bh[0], bh[1]);
                mma16816(acc[1][nt + 1], ah1, bh[2], bh[3]);
            }
        }
        __syncthreads();
    }

    const int gm   = lane >> 2;
    const int noff = (lane & 3) * 2;
#pragma unroll
    for (int ma = 0; ma < 2; ma++) {
        int pxb = m0 + ma * 64 + gm;
        int hh  = h0 + (pxb >> 6);
        int ww  = pxb & 63;
#pragma unroll
        for (int nt = 0; nt < 4; nt++) {
            int n = n0 + nt * 8 + noff;
            size_t base0 = (((size_t)(ksp * B_ + b) * CMID + n)     * H_ + hh) * W_;
            size_t base1 = (((size_t)(ksp * B_ + b) * CMID + n + 1) * H_ + hh) * W_;
            g_feat_part[base0 + ww]     = acc[ma][nt][0];
            g_feat_part[base1 + ww]     = acc[ma][nt][1];
            g_feat_part[base0 + ww + 8] = acc[ma][nt][2];
            g_feat_part[base1 + ww + 8] = acc[ma][nt][3];
        }
    }
}

// ---------------------------------------------------------------------------
// Kernel 2: combine K-split partials + bias + relu, 1x1 conv (64->100),
// bias + softmax over 100 channels, write fp16 kern.
// fs transposed [pix][k] (pad 68) so the k-loop reads float4 of f and float4
// of w per 4 k: issue per thread ~2016 vs ~3264 before.
// ---------------------------------------------------------------------------
__global__ __launch_bounds__(256) void conv1x1_softmax_kernel(
    const float* __restrict__ b1,
    const float* __restrict__ w2, const float* __restrict__ b2)
{
    __shared__ float fs[64][68];        // [pix][k], pad 68 for f4 banks
    __shared__ float w2s[NK][64];       // [j][k]
    __shared__ float redm[4][64];
    __shared__ float reds[4][64];

    const int tid = threadIdx.x;
    const int jg  = tid >> 6;
    const int pix = tid & 63;

    const int b  = blockIdx.x >> 6;
    const int p0 = (blockIdx.x & 63) * 64;

    for (int idx = tid; idx < 64 * 64; idx += 256) {
        int k = idx >> 6, i = idx & 63;
        float v = b1[k];
#pragma unroll
        for (int p = 0; p < KSPLIT; p++)
            v += g_feat_part[((size_t)(p * B_ + b) * CMID + k) * (H_ * W_) + p0 + i];
        fs[i][k] = v > 0.f ? v : 0.f;
    }
    for (int idx = tid; idx < NK * 64; idx += 256) {
        int j = idx >> 6, k = idx & 63;
        w2s[j][k] = w2[j * 64 + k];
    }
    __syncthreads();

    float acc[25];
#pragma unroll
    for (int jj = 0; jj < 25; jj++) acc[jj] = b2[jg * 25 + jj];

#pragma unroll
    for (int k0 = 0; k0 < 64; k0 += 4) {
        float4 f4 = *reinterpret_cast<const float4*>(&fs[pix][k0]);
#pragma unroll
        for (int jj = 0; jj < 25; jj++) {
            float4 w4 = *reinterpret_cast<const float4*>(&w2s[jg * 25 + jj][k0]);
            acc[jj] += f4.x * w4.x + f4.y * w4.y + f4.z * w4.z + f4.w * w4.w;
        }
    }

    float lmax = acc[0];
#pragma unroll
    for (int jj = 1; jj < 25; jj++) lmax = fmaxf(lmax, acc[jj]);
    redm[jg][pix] = lmax;
    __syncthreads();
    float gmax = fmaxf(fmaxf(redm[0][pix], redm[1][pix]),
                       fmaxf(redm[2][pix], redm[3][pix]));
    float lsum = 0.f;
#pragma unroll
    for (int jj = 0; jj < 25; jj++) {
        acc[jj] = __expf(acc[jj] - gmax);
        lsum += acc[jj];
    }
    reds[jg][pix] = lsum;
    __syncthreads();
    float gsum = reds[0][pix] + reds[1][pix] + reds[2][pix] + reds[3][pix];
    float inv = 1.f / gsum;
#pragma unroll
    for (int jj = 0; jj < 25; jj++)
        g_kh[(size_t)(b * NK + jg * 25 + jj) * (H_ * W_) + p0 + pix] =
            __float2half_rn(acc[jj] * inv);
}

// ---------------------------------------------------------------------------
// Kernel 3: reassembly + pixel shuffle (R13 structure; kern loads fp16).
// kreg2[2][25] half2 in registers; x-tile float2 in smem; 8 channels per
// k-step with acc[4][8]. grid (8,8,B*NSPLIT); block 128 = 2 cg x 64 px.
// ---------------------------------------------------------------------------
__global__ __launch_bounds__(128, 4) void reassembly_kernel(
    const float* __restrict__ x, float* __restrict__ out)
{
    __shared__ float2 xs2[16][12][24];  // [ch-pair][row][col]

    const int tid = threadIdx.x;
    const int cg  = tid >> 6;           // 0..1 -> ch-pairs [cg*8, cg*8+8)
    const int pix = tid & 63;
    const int py  = pix >> 3;
    const int px  = pix & 7;

    const int x0 = blockIdx.x * 8;
    const int y0 = blockIdx.y * 8;
    const int b  = blockIdx.z >> 2;
    const int sp = blockIdx.z & 3;
    const int gy = y0 + py, gx = x0 + px;

    // kernel weights: kreg2[p][k] = (kern[2p][k], kern[2p+1][k]) fp16
    __half2 kreg2[2][25];
#pragma unroll
    for (int p = 0; p < 2; p++)
#pragma unroll
        for (int k = 0; k < 25; k++) {
            __half ha = g_kh[(size_t)((b * NK + (2 * p) * 25 + k) * H_ + gy) * W_ + gx];
            __half hb = g_kh[(size_t)((b * NK + (2 * p + 1) * 25 + k) * H_ + gy) * W_ + gx];
            kreg2[p][k] = __halves2half2(ha, hb);
        }

    for (int c0 = sp * CSPL; c0 < sp * CSPL + CSPL; c0 += 32) {
        __syncthreads();
        for (int idx = tid; idx < 16 * 144; idx += 128) {
            int chp = idx / 144;
            int r   = (idx % 144) / 12;
            int col = idx % 12;
            int yy = y0 + r - 2;
            int xx = x0 + col - 2;
            float2 v = make_float2(0.f, 0.f);
            if (yy >= 0 && yy < H_ && xx >= 0 && xx < W_) {
                size_t base = ((size_t)(b * C_ + c0 + 2 * chp) * H_ + yy) * W_ + xx;
                v.x = x[base];
                v.y = x[base + (size_t)H_ * W_];
            }
            xs2[chp][r][col] = v;
        }
        __syncthreads();

#pragma unroll
        for (int grp = 0; grp < 2; grp++) {
            const int chp0 = cg * 8 + grp * 4;   // 4 ch-pairs = 8 channels
            float acc[4][8];
#pragma unroll
            for (int s = 0; s < 4; s++)
#pragma unroll
                for (int j = 0; j < 8; j++) acc[s][j] = 0.f;

#pragma unroll
            for (int kh = 0; kh < 5; kh++)
#pragma unroll
                for (int kw = 0; kw < 5; kw++) {
                    int k = kh * 5 + kw;
                    float2 v0 = xs2[chp0][py + kh][px + kw];
                    float2 v1 = xs2[chp0 + 1][py + kh][px + kw];
                    float2 v2 = xs2[chp0 + 2][py + kh][px + kw];
                    float2 v3 = xs2[chp0 + 3][py + kh][px + kw];
                    float2 w01 = __half22float2(kreg2[0][k]);
                    float2 w23 = __half22float2(kreg2[1][k]);
                    acc[0][0] += w01.x * v0.x; acc[0][1] += w01.x * v0.y;
                    acc[0][2] += w01.x * v1.x; acc[0][3] += w01.x * v1.y;
                    acc[0][4] += w01.x * v2.x; acc[0][5] += w01.x * v2.y;
                    acc[0][6] += w01.x * v3.x; acc[0][7] += w01.x * v3.y;
                    acc[1][0] += w01.y * v0.x; acc[1][1] += w01.y * v0.y;
                    acc[1][2] += w01.y * v1.x; acc[1][3] += w01.y * v1.y;
                    acc[1][4] += w01.y * v2.x; acc[1][5] += w01.y * v2.y;
                    acc[1][6] += w01.y * v3.x; acc[1][7] += w01.y * v3.y;
                    acc[2][0] += w23.x * v0.x; acc[2][1] += w23.x * v0.y;
                    acc[2][2] += w23.x * v1.x; acc[2][3] += w23.x * v1.y;
                    acc[2][4] += w23.x * v2.x; acc[2][5] += w23.x * v2.y;
                    acc[2][6] += w23.x * v3.x; acc[2][7] += w23.x * v3.y;
                    acc[3][0] += w23.y * v0.x; acc[3][1] += w23.y * v0.y;
                    acc[3][2] += w23.y * v1.x; acc[3][3] += w23.y * v1.y;
                    acc[3][4] += w23.y * v2.x; acc[3][5] += w23.y * v2.y;
                    acc[3][6] += w23.y * v3.x; acc[3][7] += w23.y * v3.y;
                }

            // channels c..c+7, c multiple of 8:
            // j 0..3 -> q4 = c>>2 (rows 2gy, 2gy+1); j 4..7 -> q4+1
            int c   = c0 + 2 * chp0;
            int q40 = c >> 2;
            int oy  = 2 * gy;
            int ox  = 2 * gx;
#pragma unroll
            for (int s = 0; s < 4; s++) {
                size_t base = ((size_t)(b * C_ + s * 64 + q40) * 128 + oy) * 128 + ox;
                float2 va; va.x = acc[s][0]; va.y = acc[s][1];
                float2 vb; vb.x = acc[s][2]; vb.y = acc[s][3];
                float2 vc; vc.x = acc[s][4]; vc.y = acc[s][5];
                float2 vd; vd.x = acc[s][6]; vd.y = acc[s][7];
                *reinterpret_cast<float2*>(&out[base])               = va;
                *reinterpret_cast<float2*>(&out[base + 128])         = vb;
                *reinterpret_cast<float2*>(&out[base + 16384])       = vc;
                *reinterpret_cast<float2*>(&out[base + 16384 + 128]) = vd;
            }
        }
    }
}

// ---------------------------------------------------------------------------
extern "C" void kernel_launch(void* const* d_in, const int* in_sizes, int n_in,
                              void* d_out, int out_size)
{
    const float* x  = (const float*)d_in[0];
    const float* w1 = (const float*)d_in[1];
    const float* b1 = (const float*)d_in[2];
    const float* w2 = (const float*)d_in[3];
    const float* b2 = (const float*)d_in[4];
    float* out = (float*)d_out;

    convert_kernel<<<1024, 256>>>(x, w1);
    conv3x3_hmma_kernel<<<B_ * 32 * KSPLIT, 256>>>();
    conv1x1_softmax_kernel<<<B_ * (H_ * W_) / 64, 256>>>(b1, w2, b2);

    dim3 gsplit(W_ / 8, H_ / 8, B_ * NSPLIT);
    reassembly_kernel<<<gsplit, 128>>>(x, out);
}

// round 16
// speedup vs baseline: 1.2859x; 1.2859x over previous
#include <cuda_runtime.h>
#include <cuda_fp16.h>
#include <cstdint>

// CARAFE: conv3x3 via single-pass fp16 mma.sync implicit GEMM (M=128 tiles,
// K-split x3, pre-shifted x copies), combine+bias+relu fused into
// conv1x1+softmax (float4 w reads), then 5x5 reassembly + pixel_shuffle(2).
// x(4,256,64,64) w1(64,256,3,3) b1(64) w2(100,64) b2(100) -> out(4,256,128,128)

#define B_   4
#define C_   256
#define H_   64
#define W_   64
#define CMID 64
#define NK   100
#define NSPLIT 4
#define CSPL (C_ / NSPLIT)

#define KTOT   (C_ * 9)     // 2304
#define KC     64           // k per staged chunk
#define NCHUNK (KTOT / KC)  // 36
#define KSPLIT 3
#define CHPS   (NCHUNK / KSPLIT)  // 12 chunks per CTA

#define NX (B_ * C_ * H_ * W_)   // 4194304
#define NW (CMID * KTOT)         // 147456

// scratch
__device__ float  g_feat_part[KSPLIT * B_ * CMID * H_ * W_];  // 12 MB
__device__ float  g_kern[B_ * NK * H_ * W_];
__device__ __half g_xs[3 * NX];     // 24 MB: kw-shifted fp16 x copies
__device__ __half g_wh[NW];

__device__ __forceinline__ uint32_t s2u(const void* p) {
    uint32_t a;
    asm("{ .reg .u64 t; cvta.to.shared.u64 t, %1; cvt.u32.u64 %0, t; }"
        : "=r"(a) : "l"(p));
    return a;
}
__device__ __forceinline__ void ldsm4(uint32_t* r, uint32_t addr) {
    asm volatile("ldmatrix.sync.aligned.m8n8.x4.shared.b16 {%0,%1,%2,%3}, [%4];"
                 : "=r"(r[0]), "=r"(r[1]), "=r"(r[2]), "=r"(r[3]) : "r"(addr));
}
__device__ __forceinline__ void ldsm4t(uint32_t* r, uint32_t addr) {
    asm volatile("ldmatrix.sync.aligned.m8n8.x4.trans.shared.b16 {%0,%1,%2,%3}, [%4];"
                 : "=r"(r[0]), "=r"(r[1]), "=r"(r[2]), "=r"(r[3]) : "r"(addr));
}
__device__ __forceinline__ void mma16816(float* d, const uint32_t* a,
                                         uint32_t b0, uint32_t b1) {
    asm volatile(
        "mma.sync.aligned.m16n8k16.row.col.f32.f16.f16.f32 "
        "{%0,%1,%2,%3}, {%4,%5,%6,%7}, {%8,%9}, {%0,%1,%2,%3};"
        : "+f"(d[0]), "+f"(d[1]), "+f"(d[2]), "+f"(d[3])
        : "r"(a[0]), "r"(a[1]), "r"(a[2]), "r"(a[3]), "r"(b0), "r"(b1));
}
__device__ __forceinline__ uint32_t pack2(__half a, __half b) {
    return (uint32_t)__half_as_ushort(a) | ((uint32_t)__half_as_ushort(b) << 16);
}

// ---------------------------------------------------------------------------
// Kernel 0: build g_wh and the 3 kw-shifted fp16 copies of x.
// ---------------------------------------------------------------------------
__global__ void convert_kernel(const float* __restrict__ x,
                               const float* __restrict__ w1)
{
    const int stride = gridDim.x * blockDim.x;
    const int tid0 = blockIdx.x * blockDim.x + threadIdx.x;

    for (int i = tid0; i < NW; i += stride)
        g_wh[i] = __float2half_rn(w1[i]);

    const int HALF_NX = NX / 2;
    const int n2 = 3 * HALF_NX;
    for (int i = tid0; i < n2; i += stride) {
        int kw  = i / HALF_NX;
        int rem = i - kw * HALF_NX;
        int wp  = rem & 31;
        int row = rem >> 5;
        int w0  = 2 * wp + kw - 1;
        const float* src = x + (size_t)row * W_;
        float v0 = ((unsigned)w0 < W_)       ? src[w0]     : 0.f;
        float v1 = ((unsigned)(w0 + 1) < W_) ? src[w0 + 1] : 0.f;
        uint32_t packed = pack2(__float2half_rn(v0), __float2half_rn(v1));
        *reinterpret_cast<uint32_t*>(g_xs + (size_t)kw * NX + (size_t)row * W_
                                     + 2 * wp) = packed;
    }
}

// ---------------------------------------------------------------------------
// Kernel 1: conv3x3 partial (12 K-chunks) as fp16 HMMA implicit GEMM.
// ---------------------------------------------------------------------------
__global__ __launch_bounds__(256, 2) void conv3x3_hmma_kernel()
{
    __shared__ __half ATh[KC][136];     // [k][128 px + pad]
    __shared__ __half Bsh[CMID][72];    // [n][k]

    const int tid  = threadIdx.x;
    const int lane = tid & 31;
    const int wid  = tid >> 5;

    const int bx   = blockIdx.x;
    const int b    = bx / (32 * KSPLIT);
    const int rem  = bx % (32 * KSPLIT);
    const int hp   = rem / KSPLIT;
    const int ksp  = rem % KSPLIT;
    const int h0   = hp * 2;

    const int m0 = (wid & 3) * 16;
    const int n0 = (wid >> 2) * 32;

    const int lrow  = (lane & 7) + ((lane >> 4) & 1) * 8;
    const int lcol8 = ((lane >> 3) & 1) * 8;

    const uint32_t sATh = s2u(ATh);
    const uint32_t sBh  = s2u(Bsh);

    float acc[2][4][4];
#pragma unroll
    for (int i = 0; i < 2; i++)
#pragma unroll
        for (int j = 0; j < 4; j++)
#pragma unroll
            for (int t = 0; t < 4; t++) acc[i][j][t] = 0.f;

    for (int chk = ksp * CHPS; chk < (ksp + 1) * CHPS; chk++) {
        const int k0 = chk * KC;

#pragma unroll
        for (int t = 0; t < 4; t++) {
            int idx = tid + (t << 8);
            int kk  = idx >> 4;
            int seg = idx & 15;
            int k   = k0 + kk;
            int c   = k / 9;
            int r   = k - c * 9;
            int kh  = r / 3;
            int kw  = r - kh * 3;
            int y   = h0 + (seg >> 3) + kh - 1;
            uint4 v = make_uint4(0u, 0u, 0u, 0u);
            if ((unsigned)y < H_)
                v = *reinterpret_cast<const uint4*>(
                    g_xs + ((size_t)kw * NX)
                         + (((size_t)(b * C_ + c) * H_ + y) * W_)
                         + (seg & 7) * 8);
            *reinterpret_cast<uint4*>(&ATh[kk][seg * 8]) = v;
        }
        {
            int n  = tid >> 2;
            int kq = tid & 3;
            const uint4* ph = reinterpret_cast<const uint4*>(
                g_wh + (size_t)n * KTOT + k0 + kq * 16);
            uint4 w0 = ph[0], w1v = ph[1];
            *reinterpret_cast<uint4*>(&Bsh[n][kq * 16])     = w0;
            *reinterpret_cast<uint4*>(&Bsh[n][kq * 16 + 8]) = w1v;
        }
        __syncthreads();

#pragma unroll
        for (int ks = 0; ks < 4; ks++) {
            uint32_t arow = (uint32_t)((ks * 16 + lrow) * 136);
            uint32_t ah0[4], ah1[4];
            ldsm4t(ah0, sATh + (arow + m0 + lcol8) * 2);
            ldsm4t(ah1, sATh + (arow + m0 + 64 + lcol8) * 2);
#pragma unroll
            for (int hn = 0; hn < 2; hn++) {
                uint32_t boff = (uint32_t)(((n0 + hn * 16 + lrow) * 72
                                            + ks * 16 + lcol8) * 2);
                uint32_t bh[4];
                ldsm4(bh, sBh + boff);
                int nt = hn * 2;
                mma16816(acc[0][nt],     ah0, bh[0], bh[1]);
                mma16816(acc[0][nt + 1], ah0, bh[2], bh[3]);
                mma16816(acc[1][nt],     ah1, bh[0], bh[1]);
                mma16816(acc[1][nt + 1], ah1, bh[2], bh[3]);
            }
        }
        __syncthreads();
    }

    const int gm   = lane >> 2;
    const int noff = (lane & 3) * 2;
#pragma unroll
    for (int ma = 0; ma < 2; ma++) {
        int pxb = m0 + ma * 64 + gm;
        int hh  = h0 + (pxb >> 6);
        int ww  = pxb & 63;
#pragma unroll
        for (int nt = 0; nt < 4; nt++) {
            int n = n0 + nt * 8 + noff;
            size_t base0 = (((size_t)(ksp * B_ + b) * CMID + n)     * H_ + hh) * W_;
            size_t base1 = (((size_t)(ksp * B_ + b) * CMID + n + 1) * H_ + hh) * W_;
            g_feat_part[base0 + ww]     = acc[ma][nt][0];
            g_feat_part[base1 + ww]     = acc[ma][nt][1];
            g_feat_part[base0 + ww + 8] = acc[ma][nt][2];
            g_feat_part[base1 + ww + 8] = acc[ma][nt][3];
        }
    }
}

// ---------------------------------------------------------------------------
// Kernel 2: combine K-split partials + bias + relu, 1x1 conv (64->100),
// bias + softmax over 100 channels.
// fs layout unchanged [k][pix]; w2s reads vectorized as warp-uniform float4.
// ---------------------------------------------------------------------------
__global__ __launch_bounds__(256) void conv1x1_softmax_kernel(
    const float* __restrict__ b1,
    const float* __restrict__ w2, const float* __restrict__ b2)
{
    __shared__ float fs[64][64];        // [k][pix]
    __shared__ float w2s[NK][64];       // [j][k]
    __shared__ float redm[4][64];
    __shared__ float reds[4][64];

    const int tid = threadIdx.x;
    const int jg  = tid >> 6;
    const int pix = tid & 63;

    const int b  = blockIdx.x >> 6;
    const int p0 = (blockIdx.x & 63) * 64;

    for (int idx = tid; idx < 64 * 64; idx += 256) {
        int k = idx >> 6, i = idx & 63;
        float v = b1[k];
#pragma unroll
        for (int p = 0; p < KSPLIT; p++)
            v += g_feat_part[((size_t)(p * B_ + b) * CMID + k) * (H_ * W_) + p0 + i];
        fs[k][i] = v > 0.f ? v : 0.f;
    }
    for (int idx = tid; idx < NK * 64; idx += 256) {
        int j = idx >> 6, k = idx & 63;
        w2s[j][k] = w2[j * 64 + k];
    }
    __syncthreads();

    float acc[25];
#pragma unroll
    for (int jj = 0; jj < 25; jj++) acc[jj] = b2[jg * 25 + jj];

#pragma unroll 4
    for (int k0 = 0; k0 < 64; k0 += 4) {
        float f0 = fs[k0][pix];
        float f1 = fs[k0 + 1][pix];
        float f2 = fs[k0 + 2][pix];
        float f3 = fs[k0 + 3][pix];
#pragma unroll
        for (int jj = 0; jj < 25; jj++) {
            float4 w4 = *reinterpret_cast<const float4*>(&w2s[jg * 25 + jj][k0]);
            acc[jj] += f0 * w4.x + f1 * w4.y + f2 * w4.z + f3 * w4.w;
        }
    }

    float lmax = acc[0];
#pragma unroll
    for (int jj = 1; jj < 25; jj++) lmax = fmaxf(lmax, acc[jj]);
    redm[jg][pix] = lmax;
    __syncthreads();
    float gmax = fmaxf(fmaxf(redm[0][pix], redm[1][pix]),
                       fmaxf(redm[2][pix], redm[3][pix]));
    float lsum = 0.f;
#pragma unroll
    for (int jj = 0; jj < 25; jj++) {
        acc[jj] = __expf(acc[jj] - gmax);
        lsum += acc[jj];
    }
    reds[jg][pix] = lsum;
    __syncthreads();
    float gsum = reds[0][pix] + reds[1][pix] + reds[2][pix] + reds[3][pix];
    float inv = 1.f / gsum;
#pragma unroll
    for (int jj = 0; jj < 25; jj++)
        g_kern[(b * NK + jg * 25 + jj) * (H_ * W_) + p0 + pix] = acc[jj] * inv;
}

// ---------------------------------------------------------------------------
// Kernel 3: reassembly + pixel shuffle (exact R13 version — best measured).
// kreg2[2][25] half2 in registers; x-tile float2 in smem; 8 channels per
// k-step with acc[4][8]. grid (8,8,B*NSPLIT); block 128 = 2 cg x 64 px.
// ---------------------------------------------------------------------------
__global__ __launch_bounds__(128, 4) void reassembly_kernel(
    const float* __restrict__ x, float* __restrict__ out)
{
    __shared__ float2 xs2[16][12][24];  // [ch-pair][row][col]

    const int tid = threadIdx.x;
    const int cg  = tid >> 6;           // 0..1 -> ch-pairs [cg*8, cg*8+8)
    const int pix = tid & 63;
    const int py  = pix >> 3;
    const int px  = pix & 7;

    const int x0 = blockIdx.x * 8;
    const int y0 = blockIdx.y * 8;
    const int b  = blockIdx.z >> 2;
    const int sp = blockIdx.z & 3;
    const int gy = y0 + py, gx = x0 + px;

    // kernel weights packed: kreg2[p][k] = (kern[2p][k], kern[2p+1][k]) fp16
    __half2 kreg2[2][25];
#pragma unroll
    for (int p = 0; p < 2; p++)
#pragma unroll
        for (int k = 0; k < 25; k++) {
            float wa = g_kern[((b * NK + (2 * p) * 25 + k) * H_ + gy) * W_ + gx];
            float wb = g_kern[((b * NK + (2 * p + 1) * 25 + k) * H_ + gy) * W_ + gx];
            kreg2[p][k] = __floats2half2_rn(wa, wb);
        }

    for (int c0 = sp * CSPL; c0 < sp * CSPL + CSPL; c0 += 32) {
        __syncthreads();
        for (int idx = tid; idx < 16 * 144; idx += 128) {
            int chp = idx / 144;
            int r   = (idx % 144) / 12;
            int col = idx % 12;
            int yy = y0 + r - 2;
            int xx = x0 + col - 2;
            float2 v = make_float2(0.f, 0.f);
            if (yy >= 0 && yy < H_ && xx >= 0 && xx < W_) {
                size_t base = ((size_t)(b * C_ + c0 + 2 * chp) * H_ + yy) * W_ + xx;
                v.x = x[base];
                v.y = x[base + (size_t)H_ * W_];
            }
            xs2[chp][r][col] = v;
        }
        __syncthreads();

#pragma unroll
        for (int grp = 0; grp < 2; grp++) {
            const int chp0 = cg * 8 + grp * 4;   // 4 ch-pairs = 8 channels
            float acc[4][8];
#pragma unroll
            for (int s = 0; s < 4; s++)
#pragma unroll
                for (int j = 0; j < 8; j++) acc[s][j] = 0.f;

#pragma unroll
            for (int kh = 0; kh < 5; kh++)
#pragma unroll
                for (int kw = 0; kw < 5; kw++) {
                    int k = kh * 5 + kw;
                    float2 v0 = xs2[chp0][py + kh][px + kw];
                    float2 v1 = xs2[chp0 + 1][py + kh][px + kw];
                    float2 v2 = xs2[chp0 + 2][py + kh][px + kw];
                    float2 v3 = xs2[chp0 + 3][py + kh][px + kw];
                    float2 w01 = __half22float2(kreg2[0][k]);
                    float2 w23 = __half22float2(kreg2[1][k]);
                    acc[0][0] += w01.x * v0.x; acc[0][1] += w01.x * v0.y;
                    acc[0][2] += w01.x * v1.x; acc[0][3] += w01.x * v1.y;
                    acc[0][4] += w01.x * v2.x; acc[0][5] += w01.x * v2.y;
                    acc[0][6] += w01.x * v3.x; acc[0][7] += w01.x * v3.y;
                    acc[1][0] += w01.y * v0.x; acc[1][1] += w01.y * v0.y;
                    acc[1][2] += w01.y * v1.x; acc[1][3] += w01.y * v1.y;
                    acc[1][4] += w01.y * v2.x; acc[1][5] += w01.y * v2.y;
                    acc[1][6] += w01.y * v3.x; acc[1][7] += w01.y * v3.y;
                    acc[2][0] += w23.x * v0.x; acc[2][1] += w23.x * v0.y;
                    acc[2][2] += w23.x * v1.x; acc[2][3] += w23.x * v1.y;
                    acc[2][4] += w23.x * v2.x; acc[2][5] += w23.x * v2.y;
                    acc[2][6] += w23.x * v3.x; acc[2][7] += w23.x * v3.y;
                    acc[3][0] += w23.y * v0.x; acc[3][1] += w23.y * v0.y;
                    acc[3][2] += w23.y * v1.x; acc[3][3] += w23.y * v1.y;
                    acc[3][4] += w23.y * v2.x; acc[3][5] += w23.y * v2.y;
                    acc[3][6] += w23.y * v3.x; acc[3][7] += w23.y * v3.y;
                }

            // channels c..c+7, c multiple of 8:
            // j 0..3 -> q4 = c>>2 (rows 2gy, 2gy+1); j 4..7 -> q4+1
            int c   = c0 + 2 * chp0;
            int q40 = c >> 2;
            int oy  = 2 * gy;
            int ox  = 2 * gx;
#pragma unroll
            for (int s = 0; s < 4; s++) {
                size_t base = ((size_t)(b * C_ + s * 64 + q40) * 128 + oy) * 128 + ox;
                float2 va; va.x = acc[s][0]; va.y = acc[s][1];
                float2 vb; vb.x = acc[s][2]; vb.y = acc[s][3];
                float2 vc; vc.x = acc[s][4]; vc.y = acc[s][5];
                float2 vd; vd.x = acc[s][6]; vd.y = acc[s][7];
                *reinterpret_cast<float2*>(&out[base])               = va;
                *reinterpret_cast<float2*>(&out[base + 128])         = vb;
                *reinterpret_cast<float2*>(&out[base + 16384])       = vc;
                *reinterpret_cast<float2*>(&out[base + 16384 + 128]) = vd;
            }
        }
    }
}

// ---------------------------------------------------------------------------
extern "C" void kernel_launch(void* const* d_in, const int* in_sizes, int n_in,
                              void* d_out, int out_size)
{
    const float* x  = (const float*)d_in[0];
    const float* w1 = (const float*)d_in[1];
    const float* b1 = (const float*)d_in[2];
    const float* w2 = (const float*)d_in[3];
    const float* b2 = (const float*)d_in[4];
    float* out = (float*)d_out;

    convert_kernel<<<1024, 256>>>(x, w1);
    conv3x3_hmma_kernel<<<B_ * 32 * KSPLIT, 256>>>();
    conv1x1_softmax_kernel<<<B_ * (H_ * W_) / 64, 256>>>(b1, w2, b2);

    dim3 gsplit(W_ / 8, H_ / 8, B_ * NSPLIT);
    reassembly_kernel<<<gsplit, 128>>>(x, out);
}

// round 17
// speedup vs baseline: 1.4351x; 1.1160x over previous
#include <cuda_runtime.h>
#include <cuda_fp16.h>
#include <cstdint>

// CARAFE: conv3x3 via single-pass fp16 mma.sync implicit GEMM (M=128 tiles,
// K-split x3, pre-shifted x copies, cp.async double-buffered staging),
// combine+bias+relu fused into conv1x1+softmax (float4 w reads), then 5x5
// reassembly + pixel_shuffle(2).
// x(4,256,64,64) w1(64,256,3,3) b1(64) w2(100,64) b2(100) -> out(4,256,128,128)

#define B_   4
#define C_   256
#define H_   64
#define W_   64
#define CMID 64
#define NK   100
#define NSPLIT 4
#define CSPL (C_ / NSPLIT)

#define KTOT   (C_ * 9)     // 2304
#define KC     64           // k per staged chunk
#define NCHUNK (KTOT / KC)  // 36
#define KSPLIT 3
#define CHPS   (NCHUNK / KSPLIT)  // 12 chunks per CTA

#define NX (B_ * C_ * H_ * W_)   // 4194304
#define NW (CMID * KTOT)         // 147456

// conv smem layout (dynamic): A double buf then B double buf
#define A_BUF_BYTES (KC * 136 * 2)          // 17408
#define B_BUF_BYTES (CMID * 72 * 2)         // 9216
#define B_BASE      (2 * A_BUF_BYTES)       // 34816
#define CONV_SMEM   (B_BASE + 2 * B_BUF_BYTES)  // 53248

// scratch
__device__ float  g_feat_part[KSPLIT * B_ * CMID * H_ * W_];  // 12 MB
__device__ float  g_kern[B_ * NK * H_ * W_];
__device__ __align__(16) __half g_xs[3 * NX];   // 24 MB: kw-shifted fp16 x
__device__ __align__(16) __half g_wh[NW];

__device__ __forceinline__ uint32_t s2u(const void* p) {
    uint32_t a;
    asm("{ .reg .u64 t; cvta.to.shared.u64 t, %1; cvt.u32.u64 %0, t; }"
        : "=r"(a) : "l"(p));
    return a;
}
__device__ __forceinline__ void ldsm4(uint32_t* r, uint32_t addr) {
    asm volatile("ldmatrix.sync.aligned.m8n8.x4.shared.b16 {%0,%1,%2,%3}, [%4];"
                 : "=r"(r[0]), "=r"(r[1]), "=r"(r[2]), "=r"(r[3]) : "r"(addr));
}
__device__ __forceinline__ void ldsm4t(uint32_t* r, uint32_t addr) {
    asm volatile("ldmatrix.sync.aligned.m8n8.x4.trans.shared.b16 {%0,%1,%2,%3}, [%4];"
                 : "=r"(r[0]), "=r"(r[1]), "=r"(r[2]), "=r"(r[3]) : "r"(addr));
}
__device__ __forceinline__ void mma16816(float* d, const uint32_t* a,
                                         uint32_t b0, uint32_t b1) {
    asm volatile(
        "mma.sync.aligned.m16n8k16.row.col.f32.f16.f16.f32 "
        "{%0,%1,%2,%3}, {%4,%5,%6,%7}, {%8,%9}, {%0,%1,%2,%3};"
        : "+f"(d[0]), "+f"(d[1]), "+f"(d[2]), "+f"(d[3])
        : "r"(a[0]), "r"(a[1]), "r"(a[2]), "r"(a[3]), "r"(b0), "r"(b1));
}
__device__ __forceinline__ uint32_t pack2(__half a, __half b) {
    return (uint32_t)__half_as_ushort(a) | ((uint32_t)__half_as_ushort(b) << 16);
}
__device__ __forceinline__ void cpa16(uint32_t dst, const void* src, int sz) {
    asm volatile("cp.async.ca.shared.global [%0], [%1], 16, %2;"
                 :: "r"(dst), "l"(src), "r"(sz) : "memory");
}

// ---------------------------------------------------------------------------
// Kernel 0: build g_wh and the 3 kw-shifted fp16 copies of x.
// Each thread: one 8-px segment read ONCE (2 float4 + 2 scalars), three
// shifted uint4 stores.
// ---------------------------------------------------------------------------
__global__ void convert_kernel(const float* __restrict__ x,
                               const float* __restrict__ w1)
{
    const int stride = gridDim.x * blockDim.x;
    const int tid0 = blockIdx.x * blockDim.x + threadIdx.x;

    for (int i = tid0; i < NW; i += stride)
        g_wh[i] = __float2half_rn(w1[i]);

    const int NSEG = NX / 8;            // 524288 segments of 8 px
    for (int i = tid0; i < NSEG; i += stride) {
        int s   = i & 7;                // segment in row
        int row = i >> 3;               // (b*C + c)*H + h
        const float* src = x + (size_t)row * W_ + s * 8;
        float4 a = *reinterpret_cast<const float4*>(src);
        float4 d = *reinterpret_cast<const float4*>(src + 4);
        float lf = (s > 0) ? src[-1] : 0.f;
        float rt = (s < 7) ? src[8]  : 0.f;

        __half hl = __float2half_rn(lf);
        __half h0 = __float2half_rn(a.x), h1 = __float2half_rn(a.y);
        __half h2 = __float2half_rn(a.z), h3 = __float2half_rn(a.w);
        __half h4 = __float2half_rn(d.x), h5 = __float2half_rn(d.y);
        __half h6 = __float2half_rn(d.z), h7 = __float2half_rn(d.w);
        __half hr = __float2half_rn(rt);

        size_t off = (size_t)row * W_ + s * 8;
        // kw=1 (no shift)
        *reinterpret_cast<uint4*>(g_xs + NX + off) =
            make_uint4(pack2(h0, h1), pack2(h2, h3), pack2(h4, h5), pack2(h6, h7));
        // kw=0 (out[w] = x[w-1])
        *reinterpret_cast<uint4*>(g_xs + off) =
            make_uint4(pack2(hl, h0), pack2(h1, h2), pack2(h3, h4), pack2(h5, h6));
        // kw=2 (out[w] = x[w+1])
        *reinterpret_cast<uint4*>(g_xs + 2 * (size_t)NX + off) =
            make_uint4(pack2(h1, h2), pack2(h3, h4), pack2(h5, h6), pack2(h7, hr));
    }
}

// ---------------------------------------------------------------------------
// Kernel 1: conv3x3 partial (12 K-chunks) as fp16 HMMA implicit GEMM with
// cp.async double-buffered staging. Dynamic smem (53 KB).
// ---------------------------------------------------------------------------
__global__ __launch_bounds__(256, 2) void conv3x3_hmma_kernel()
{
    extern __shared__ char smem[];
    const uint32_t sbase = s2u(smem);

    const int tid  = threadIdx.x;
    const int lane = tid & 31;
    const int wid  = tid >> 5;

    const int bx   = blockIdx.x;
    const int b    = bx / (32 * KSPLIT);
    const int rem  = bx % (32 * KSPLIT);
    const int hp   = rem / KSPLIT;
    const int ksp  = rem % KSPLIT;
    const int h0   = hp * 2;

    const int m0 = (wid & 3) * 16;
    const int n0 = (wid >> 2) * 32;

    const int lrow  = (lane & 7) + ((lane >> 4) & 1) * 8;
    const int lcol8 = ((lane >> 3) & 1) * 8;

    float acc[2][4][4];
#pragma unroll
    for (int i = 0; i < 2; i++)
#pragma unroll
        for (int j = 0; j < 4; j++)
#pragma unroll
            for (int t = 0; t < 4; t++) acc[i][j][t] = 0.f;

    // stage chunk -> buffer via cp.async (4 A copies + 2 B copies / thread)
    auto stage = [&](int buf, int k0) {
#pragma unroll
        for (int t = 0; t < 4; t++) {
            int idx = tid + (t << 8);
            int kk  = idx >> 4;
            int seg = idx & 15;
            int k   = k0 + kk;
            int c   = k / 9;
            int r   = k - c * 9;
            int kh  = r / 3;
            int kw  = r - kh * 3;
            int y   = h0 + (seg >> 3) + kh - 1;
            int yc  = (y < 0) ? 0 : (y >= H_ ? H_ - 1 : y);
            const __half* g = g_xs + (size_t)kw * NX
                            + ((size_t)(b * C_ + c) * H_ + yc) * W_ + (seg & 7) * 8;
            uint32_t dst = sbase + buf * A_BUF_BYTES + (kk * 136 + seg * 8) * 2;
            cpa16(dst, g, ((unsigned)y < H_) ? 16 : 0);
        }
#pragma unroll
        for (int t = 0; t < 2; t++) {
            int idx = tid + (t << 8);
            int n = idx >> 3;
            int q = idx & 7;
            const __half* g = g_wh + (size_t)n * KTOT + k0 + q * 8;
            uint32_t dst = sbase + B_BASE + buf * B_BUF_BYTES + (n * 72 + q * 8) * 2;
            cpa16(dst, g, 16);
        }
        asm volatile("cp.async.commit_group;" ::: "memory");
    };

    const int chk0 = ksp * CHPS;
    stage(0, chk0 * KC);

    for (int i = 0; i < CHPS; i++) {
        const int cur = i & 1;
        asm volatile("cp.async.wait_group 0;" ::: "memory");
        __syncthreads();
        if (i + 1 < CHPS) stage(cur ^ 1, (chk0 + i + 1) * KC);

        const uint32_t aBase = sbase + cur * A_BUF_BYTES;
        const uint32_t bBase = sbase + B_BASE + cur * B_BUF_BYTES;
#pragma unroll
        for (int ks = 0; ks < 4; ks++) {
            uint32_t arow = (uint32_t)((ks * 16 + lrow) * 136);
            uint32_t ah0[4], ah1[4];
            ldsm4t(ah0, aBase + (arow + m0 + lcol8) * 2);
            ldsm4t(ah1, aBase + (arow + m0 + 64 + lcol8) * 2);
#pragma unroll
            for (int hn = 0; hn < 2; hn++) {
                uint32_t boff = (uint32_t)(((n0 + hn * 16 + lrow) * 72
                                            + ks * 16 + lcol8) * 2);
                uint32_t bh[4];
                ldsm4(bh, bBase + boff);
                int nt = hn * 2;
                mma16816(acc[0][nt],     ah0, bh[0], bh[1]);
                mma16816(acc[0][nt + 1], ah0, bh[2], bh[3]);
                mma16816(acc[1][nt],     ah1, bh[0], bh[1]);
                mma16816(acc[1][nt + 1], ah1, bh[2], bh[3]);
            }
        }
    }

    const int gm   = lane >> 2;
    const int noff = (lane & 3) * 2;
#pragma unroll
    for (int ma = 0; ma < 2; ma++) {
        int pxb = m0 + ma * 64 + gm;
        int hh  = h0 + (pxb >> 6);
        int ww  = pxb & 63;
#pragma unroll
        for (int nt = 0; nt < 4; nt++) {
            int n = n0 + nt * 8 + noff;
            size_t base0 = (((size_t)(ksp * B_ + b) * CMID + n)     * H_ + hh) * W_;
            size_t base1 = (((size_t)(ksp * B_ + b) * CMID + n + 1) * H_ + hh) * W_;
            g_feat_part[base0 + ww]     = acc[ma][nt][0];
            g_feat_part[base1 + ww]     = acc[ma][nt][1];
            g_feat_part[base0 + ww + 8] = acc[ma][nt][2];
            g_feat_part[base1 + ww + 8] = acc[ma][nt][3];
        }
    }
}

// ---------------------------------------------------------------------------
// Kernel 2: combine K-split partials + bias + relu, 1x1 conv (64->100),
// bias + softmax over 100 channels. float4 warp-uniform w reads.
// ---------------------------------------------------------------------------
__global__ __launch_bounds__(256) void conv1x1_softmax_kernel(
    const float* __restrict__ b1,
    const float* __restrict__ w2, const float* __restrict__ b2)
{
    __shared__ float fs[64][64];        // [k][pix]
    __shared__ float w2s[NK][64];       // [j][k]
    __shared__ float redm[4][64];
    __shared__ float reds[4][64];

    const int tid = threadIdx.x;
    const int jg  = tid >> 6;
    const int pix = tid & 63;

    const int b  = blockIdx.x >> 6;
    const int p0 = (blockIdx.x & 63) * 64;

    for (int idx = tid; idx < 64 * 64; idx += 256) {
        int k = idx >> 6, i = idx & 63;
        float v = b1[k];
#pragma unroll
        for (int p = 0; p < KSPLIT; p++)
            v += g_feat_part[((size_t)(p * B_ + b) * CMID + k) * (H_ * W_) + p0 + i];
        fs[k][i] = v > 0.f ? v : 0.f;
    }
    for (int idx = tid; idx < NK * 64; idx += 256) {
        int j = idx >> 6, k = idx & 63;
        w2s[j][k] = w2[j * 64 + k];
    }
    __syncthreads();

    float acc[25];
#pragma unroll
    for (int jj = 0; jj < 25; jj++) acc[jj] = b2[jg * 25 + jj];

#pragma unroll 4
    for (int k0 = 0; k0 < 64; k0 += 4) {
        float f0 = fs[k0][pix];
        float f1 = fs[k0 + 1][pix];
        float f2 = fs[k0 + 2][pix];
        float f3 = fs[k0 + 3][pix];
#pragma unroll
        for (int jj = 0; jj < 25; jj++) {
            float4 w4 = *reinterpret_cast<const float4*>(&w2s[jg * 25 + jj][k0]);
            acc[jj] += f0 * w4.x + f1 * w4.y + f2 * w4.z + f3 * w4.w;
        }
    }

    float lmax = acc[0];
#pragma unroll
    for (int jj = 1; jj < 25; jj++) lmax = fmaxf(lmax, acc[jj]);
    redm[jg][pix] = lmax;
    __syncthreads();
    float gmax = fmaxf(fmaxf(redm[0][pix], redm[1][pix]),
                       fmaxf(redm[2][pix], redm[3][pix]));
    float lsum = 0.f;
#pragma unroll
    for (int jj = 0; jj < 25; jj++) {
        acc[jj] = __expf(acc[jj] - gmax);
        lsum += acc[jj];
    }
    reds[jg][pix] = lsum;
    __syncthreads();
    float gsum = reds[0][pix] + reds[1][pix] + reds[2][pix] + reds[3][pix];
    float inv = 1.f / gsum;
#pragma unroll
    for (int jj = 0; jj < 25; jj++)
        g_kern[(b * NK + jg * 25 + jj) * (H_ * W_) + p0 + pix] = acc[jj] * inv;
}

// ---------------------------------------------------------------------------
// Kernel 3: reassembly + pixel shuffle (exact R13 version — best measured).
// ---------------------------------------------------------------------------
__global__ __launch_bounds__(128, 4) void reassembly_kernel(
    const float* __restrict__ x, float* __restrict__ out)
{
    __shared__ float2 xs2[16][12][24];  // [ch-pair][row][col]

    const int tid = threadIdx.x;
    const int cg  = tid >> 6;           // 0..1 -> ch-pairs [cg*8, cg*8+8)
    const int pix = tid & 63;
    const int py  = pix >> 3;
    const int px  = pix & 7;

    const int x0 = blockIdx.x * 8;
    const int y0 = blockIdx.y * 8;
    const int b  = blockIdx.z >> 2;
    const int sp = blockIdx.z & 3;
    const int gy = y0 + py, gx = x0 + px;

    __half2 kreg2[2][25];
#pragma unroll
    for (int p = 0; p < 2; p++)
#pragma unroll
        for (int k = 0; k < 25; k++) {
            float wa = g_kern[((b * NK + (2 * p) * 25 + k) * H_ + gy) * W_ + gx];
            float wb = g_kern[((b * NK + (2 * p + 1) * 25 + k) * H_ + gy) * W_ + gx];
            kreg2[p][k] = __floats2half2_rn(wa, wb);
        }

    for (int c0 = sp * CSPL; c0 < sp * CSPL + CSPL; c0 += 32) {
        __syncthreads();
        for (int idx = tid; idx < 16 * 144; idx += 128) {
            int chp = idx / 144;
            int r   = (idx % 144) / 12;
            int col = idx % 12;
            int yy = y0 + r - 2;
            int xx = x0 + col - 2;
            float2 v = make_float2(0.f, 0.f);
            if (yy >= 0 && yy < H_ && xx >= 0 && xx < W_) {
                size_t base = ((size_t)(b * C_ + c0 + 2 * chp) * H_ + yy) * W_ + xx;
                v.x = x[base];
                v.y = x[base + (size_t)H_ * W_];
            }
            xs2[chp][r][col] = v;
        }
        __syncthreads();

#pragma unroll
        for (int grp = 0; grp < 2; grp++) {
            const int chp0 = cg * 8 + grp * 4;
            float acc[4][8];
#pragma unroll
            for (int s = 0; s < 4; s++)
#pragma unroll
                for (int j = 0; j < 8; j++) acc[s][j] = 0.f;

#pragma unroll
            for (int kh = 0; kh < 5; kh++)
#pragma unroll
                for (int kw = 0; kw < 5; kw++) {
                    int k = kh * 5 + kw;
                    float2 v0 = xs2[chp0][py + kh][px + kw];
                    float2 v1 = xs2[chp0 + 1][py + kh][px + kw];
                    float2 v2 = xs2[chp0 + 2][py + kh][px + kw];
                    float2 v3 = xs2[chp0 + 3][py + kh][px + kw];
                    float2 w01 = __half22float2(kreg2[0][k]);
                    float2 w23 = __half22float2(kreg2[1][k]);
                    acc[0][0] += w01.x * v0.x; acc[0][1] += w01.x * v0.y;
                    acc[0][2] += w01.x * v1.x; acc[0][3] += w01.x * v1.y;
                    acc[0][4] += w01.x * v2.x; acc[0][5] += w01.x * v2.y;
                    acc[0][6] += w01.x * v3.x; acc[0][7] += w01.x * v3.y;
                    acc[1][0] += w01.y * v0.x; acc[1][1] += w01.y * v0.y;
                    acc[1][2] += w01.y * v1.x; acc[1][3] += w01.y * v1.y;
                    acc[1][4] += w01.y * v2.x; acc[1][5] += w01.y * v2.y;
                    acc[1][6] += w01.y * v3.x; acc[1][7] += w01.y * v3.y;
                    acc[2][0] += w23.x * v0.x; acc[2][1] += w23.x * v0.y;
                    acc[2][2] += w23.x * v1.x; acc[2][3] += w23.x * v1.y;
                    acc[2][4] += w23.x * v2.x; acc[2][5] += w23.x * v2.y;
                    acc[2][6] += w23.x * v3.x; acc[2][7] += w23.x * v3.y;
                    acc[3][0] += w23.y * v0.x; acc[3][1] += w23.y * v0.y;
                    acc[3][2] += w23.y * v1.x; acc[3][3] += w23.y * v1.y;
                    acc[3][4] += w23.y * v2.x; acc[3][5] += w23.y * v2.y;
                    acc[3][6] += w23.y * v3.x; acc[3][7] += w23.y * v3.y;
                }

            int c   = c0 + 2 * chp0;
            int q40 = c >> 2;
            int oy  = 2 * gy;
            int ox  = 2 * gx;
#pragma unroll
            for (int s = 0; s < 4; s++) {
                size_t base = ((size_t)(b * C_ + s * 64 + q40) * 128 + oy) * 128 + ox;
                float2 va; va.x = acc[s][0]; va.y = acc[s][1];
                float2 vb; vb.x = acc[s][2]; vb.y = acc[s][3];
                float2 vc; vc.x = acc[s][4]; vc.y = acc[s][5];
                float2 vd; vd.x = acc[s][6]; vd.y = acc[s][7];
                *reinterpret_cast<float2*>(&out[base])               = va;
                *reinterpret_cast<float2*>(&out[base + 128])         = vb;
                *reinterpret_cast<float2*>(&out[base + 16384])       = vc;
                *reinterpret_cast<float2*>(&out[base + 16384 + 128]) = vd;
            }
        }
    }
}

// ---------------------------------------------------------------------------
extern "C" void kernel_launch(void* const* d_in, const int* in_sizes, int n_in,
                              void* d_out, int out_size)
{
    const float* x  = (const float*)d_in[0];
    const float* w1 = (const float*)d_in[1];
    const float* b1 = (const float*)d_in[2];
    const float* w2 = (const float*)d_in[3];
    const float* b2 = (const float*)d_in[4];
    float* out = (float*)d_out;

    cudaFuncSetAttribute(conv3x3_hmma_kernel,
                         cudaFuncAttributeMaxDynamicSharedMemorySize, CONV_SMEM);

    convert_kernel<<<1024, 256>>>(x, w1);
    conv3x3_hmma_kernel<<<B_ * 32 * KSPLIT, 256, CONV_SMEM>>>();
    conv1x1_softmax_kernel<<<B_ * (H_ * W_) / 64, 256>>>(b1, w2, b2);

    dim3 gsplit(W_ / 8, H_ / 8, B_ * NSPLIT);
    reassembly_kernel<<<gsplit, 128>>>(x, out);
}